// round 3
// baseline (speedup 1.0000x reference)
#include <cuda_runtime.h>
#include <math_constants.h>

#define DIN  256
#define DOUT 128
#define NMAX 100000
#define EMAX 3200000
#define ALPHA 0.2f

// ---- scratch (static device globals; no allocation) ----
__device__ float  g_seq[(size_t)NMAX * DOUT];  // seq_fts = feat @ W
__device__ float  g_f1[NMAX];
__device__ float  g_f2[NMAX];
__device__ float  g_s[NMAX];                   // per-row sum of exp(logit)
__device__ int    g_cnt[NMAX];                 // per-row edge count
__device__ int    g_off[NMAX];                 // exclusive prefix (row start)
__device__ int    g_cur[NMAX];                 // scatter cursor; ends as row end
__device__ int    g_bsum[512];                 // scan block partials
__device__ float2 g_epair[EMAX];               // CSR: (col as int bits, e=exp(logit))

// ---------------------------------------------------------------------------
// 0) init: s = 0, cnt = 0
__global__ void k_init(int n) {
    int i = blockIdx.x * blockDim.x + threadIdx.x;
    if (i < n) { g_s[i] = 0.0f; g_cnt[i] = 0; }
}

// ---------------------------------------------------------------------------
// 1) SGEMM (double-buffered) + fused f1/f2 epilogue
#define BM 128
#define BN 128
#define BK 16
__global__ __launch_bounds__(256) void k_gemm(const float* __restrict__ A,
                                              const float* __restrict__ W,
                                              const float* __restrict__ al_w,
                                              const float* __restrict__ al_b,
                                              const float* __restrict__ ar_w,
                                              const float* __restrict__ ar_b,
                                              int n) {
    __shared__ float As[2][BK][BM];
    __shared__ float Ws[2][BK][BN];
    int tid = threadIdx.x;
    int tx = tid & 15;
    int ty = tid >> 4;
    int rowBase = blockIdx.x * BM;

    float4 rA[2], rW[2];

    auto loadA = [&](int k0) {
        #pragma unroll
        for (int i = 0; i < 2; i++) {
            int t  = tid + i * 256;
            int m  = t >> 2;
            int kq = (t & 3) * 4;
            int gr = rowBase + m;
            rA[i] = make_float4(0.f, 0.f, 0.f, 0.f);
            if (gr < n) rA[i] = *(const float4*)(A + (size_t)gr * DIN + k0 + kq);
        }
    };
    auto loadW = [&](int k0) {
        #pragma unroll
        for (int i = 0; i < 2; i++) {
            int t  = tid + i * 256;
            int kk = t >> 5;
            int nq = (t & 31) * 4;
            rW[i] = *(const float4*)(W + (size_t)(k0 + kk) * DOUT + nq);
        }
    };
    auto storeTiles = [&](int b) {
        #pragma unroll
        for (int i = 0; i < 2; i++) {
            int t  = tid + i * 256;
            int m  = t >> 2;
            int kq = (t & 3) * 4;
            As[b][kq + 0][m] = rA[i].x; As[b][kq + 1][m] = rA[i].y;
            As[b][kq + 2][m] = rA[i].z; As[b][kq + 3][m] = rA[i].w;
            int kk = t >> 5;
            int nq = (t & 31) * 4;
            *(float4*)&Ws[b][kk][nq] = rW[i];
        }
    };

    float acc[8][8];
    #pragma unroll
    for (int i = 0; i < 8; i++)
        #pragma unroll
        for (int j = 0; j < 8; j++) acc[i][j] = 0.0f;

    loadA(0); loadW(0);
    storeTiles(0);
    __syncthreads();

    int buf = 0;
    const int NT = DIN / BK;   // 16
    for (int t = 0; t < NT; t++) {
        if (t + 1 < NT) { loadA((t + 1) * BK); loadW((t + 1) * BK); }

        #pragma unroll
        for (int k = 0; k < BK; k++) {
            float ra[8], rb[8];
            #pragma unroll
            for (int i = 0; i < 8; i++) ra[i] = As[buf][k][ty * 8 + i];
            #pragma unroll
            for (int j = 0; j < 4; j++) {
                rb[j]     = Ws[buf][k][tx * 4 + j];
                rb[j + 4] = Ws[buf][k][64 + tx * 4 + j];
            }
            #pragma unroll
            for (int i = 0; i < 8; i++)
                #pragma unroll
                for (int j = 0; j < 8; j++)
                    acc[i][j] += ra[i] * rb[j];
        }

        if (t + 1 < NT) {
            storeTiles(buf ^ 1);
            __syncthreads();
            buf ^= 1;
        }
    }

    // store seq_fts
    #pragma unroll
    for (int i = 0; i < 8; i++) {
        int gr = rowBase + ty * 8 + i;
        if (gr < n) {
            float* dst = g_seq + (size_t)gr * DOUT;
            *(float4*)(dst + tx * 4)      = make_float4(acc[i][0], acc[i][1], acc[i][2], acc[i][3]);
            *(float4*)(dst + 64 + tx * 4) = make_float4(acc[i][4], acc[i][5], acc[i][6], acc[i][7]);
        }
    }

    // fused f1/f2: dot each output row with al_w / ar_w, reduce across the
    // 16 tx-threads (one 16-lane half-warp per row group)
    float4 a_lo = *(const float4*)(al_w + tx * 4);
    float4 a_hi = *(const float4*)(al_w + 64 + tx * 4);
    float4 r_lo = *(const float4*)(ar_w + tx * 4);
    float4 r_hi = *(const float4*)(ar_w + 64 + tx * 4);
    float ab = al_b[0], rb2 = ar_b[0];

    #pragma unroll
    for (int i = 0; i < 8; i++) {
        float s1 = acc[i][0] * a_lo.x + acc[i][1] * a_lo.y + acc[i][2] * a_lo.z + acc[i][3] * a_lo.w
                 + acc[i][4] * a_hi.x + acc[i][5] * a_hi.y + acc[i][6] * a_hi.z + acc[i][7] * a_hi.w;
        float s2 = acc[i][0] * r_lo.x + acc[i][1] * r_lo.y + acc[i][2] * r_lo.z + acc[i][3] * r_lo.w
                 + acc[i][4] * r_hi.x + acc[i][5] * r_hi.y + acc[i][6] * r_hi.z + acc[i][7] * r_hi.w;
        #pragma unroll
        for (int o = 8; o > 0; o >>= 1) {
            s1 += __shfl_xor_sync(0xFFFFFFFFu, s1, o);
            s2 += __shfl_xor_sync(0xFFFFFFFFu, s2, o);
        }
        if (tx == 0) {
            int gr = rowBase + ty * 8 + i;
            if (gr < n) { g_f1[gr] = s1 + ab; g_f2[gr] = s2 + rb2; }
        }
    }
}

// ---------------------------------------------------------------------------
// 2) edge pass 1: per-row edge count only (reads just `row`, vectorized x4)
__global__ void k_edge1(const int* __restrict__ row, int e) {
    int i = (blockIdx.x * blockDim.x + threadIdx.x) * 4;
    if (i + 4 <= e) {
        int4 r4 = *(const int4*)(row + i);
        atomicAdd(&g_cnt[r4.x], 1);
        atomicAdd(&g_cnt[r4.y], 1);
        atomicAdd(&g_cnt[r4.z], 1);
        atomicAdd(&g_cnt[r4.w], 1);
    } else {
        for (int k = i; k < e; k++) atomicAdd(&g_cnt[row[k]], 1);
    }
}

// ---------------------------------------------------------------------------
// 3) 3-kernel exclusive scan over g_cnt -> g_off (+ g_cur copy)
__global__ void k_scan1(int n) {
    __shared__ int sh[256];
    int t = threadIdx.x;
    int i = blockIdx.x * 256 + t;
    int v = (i < n) ? g_cnt[i] : 0;
    sh[t] = v;
    __syncthreads();
    #pragma unroll
    for (int o = 1; o < 256; o <<= 1) {
        int x = (t >= o) ? sh[t - o] : 0;
        __syncthreads();
        sh[t] += x;
        __syncthreads();
    }
    if (i < n) g_off[i] = sh[t] - v;
    if (t == 255) g_bsum[blockIdx.x] = sh[255];
}

__global__ void k_scan2(int nblk) {
    __shared__ int sh[512];
    int t = threadIdx.x;
    int v = (t < nblk) ? g_bsum[t] : 0;
    sh[t] = v;
    __syncthreads();
    #pragma unroll
    for (int o = 1; o < 512; o <<= 1) {
        int x = (t >= o) ? sh[t - o] : 0;
        __syncthreads();
        sh[t] += x;
        __syncthreads();
    }
    if (t < nblk) g_bsum[t] = sh[t] - v;
}

__global__ void k_scan3(int n) {
    int i = blockIdx.x * blockDim.x + threadIdx.x;
    if (i >= n) return;
    int o = g_off[i] + g_bsum[i >> 8];
    g_off[i] = o;
    g_cur[i] = o;
}

// ---------------------------------------------------------------------------
// 4) edge pass 2: e = exp(leaky_relu(f1[r]+f2[c])); accumulate s; scatter (c,e)
__global__ void k_edge2(const int* __restrict__ row, const int* __restrict__ col, int e) {
    int i = blockIdx.x * blockDim.x + threadIdx.x;
    if (i >= e) return;
    int r = row[i], c = col[i];
    float x = g_f1[r] + g_f2[c];
    float l = x > 0.0f ? x : ALPHA * x;
    float ev = __expf(l);
    atomicAdd(&g_s[r], ev);
    int pos = atomicAdd(&g_cur[r], 1);
    g_epair[pos] = make_float2(__int_as_float(c), ev);
}

// ---------------------------------------------------------------------------
// 5) CSR SpMM: one warp per node; out = (Σ e_j * seq[c_j]) / s + bias
__global__ __launch_bounds__(256) void k_spmm(const float* __restrict__ bias,
                                              float* __restrict__ out, int n) {
    int gw   = (blockIdx.x * blockDim.x + threadIdx.x) >> 5;
    int lane = threadIdx.x & 31;
    if (gw >= n) return;
    int j0  = g_off[gw];
    int end = g_cur[gw];
    int j   = j0;

    float4 acc = make_float4(0.f, 0.f, 0.f, 0.f);

    for (; j + 4 <= end; j += 4) {
        float2 p0 = g_epair[j],     p1 = g_epair[j + 1];
        float2 p2 = g_epair[j + 2], p3 = g_epair[j + 3];
        float4 v0 = ((const float4*)(g_seq + (size_t)__float_as_int(p0.x) * DOUT))[lane];
        float4 v1 = ((const float4*)(g_seq + (size_t)__float_as_int(p1.x) * DOUT))[lane];
        float4 v2 = ((const float4*)(g_seq + (size_t)__float_as_int(p2.x) * DOUT))[lane];
        float4 v3 = ((const float4*)(g_seq + (size_t)__float_as_int(p3.x) * DOUT))[lane];
        acc.x += p0.y * v0.x + p1.y * v1.x + p2.y * v2.x + p3.y * v3.x;
        acc.y += p0.y * v0.y + p1.y * v1.y + p2.y * v2.y + p3.y * v3.y;
        acc.z += p0.y * v0.z + p1.y * v1.z + p2.y * v2.z + p3.y * v3.z;
        acc.w += p0.y * v0.w + p1.y * v1.w + p2.y * v2.w + p3.y * v3.w;
    }
    for (; j < end; j++) {
        float2 p = g_epair[j];
        float4 v = ((const float4*)(g_seq + (size_t)__float_as_int(p.x) * DOUT))[lane];
        acc.x += p.y * v.x; acc.y += p.y * v.y;
        acc.z += p.y * v.z; acc.w += p.y * v.w;
    }

    float inv = (end > j0) ? 1.0f / g_s[gw] : 0.0f;
    float4 b = ((const float4*)bias)[lane];
    acc.x = acc.x * inv + b.x;
    acc.y = acc.y * inv + b.y;
    acc.z = acc.z * inv + b.z;
    acc.w = acc.w * inv + b.w;
    ((float4*)(out + (size_t)gw * DOUT))[lane] = acc;
}

// ---------------------------------------------------------------------------
extern "C" void kernel_launch(void* const* d_in, const int* in_sizes, int n_in,
                              void* d_out, int out_size) {
    const float* feat = (const float*)d_in[0];
    const int*   row  = (const int*)  d_in[1];
    const int*   col  = (const int*)  d_in[2];
    const float* W    = (const float*)d_in[3];
    const float* al_w = (const float*)d_in[4];
    const float* al_b = (const float*)d_in[5];
    const float* ar_w = (const float*)d_in[6];
    const float* ar_b = (const float*)d_in[7];
    const float* bias = (const float*)d_in[8];
    float* out = (float*)d_out;

    int n = in_sizes[0] / DIN;   // 100000
    int e = in_sizes[1];         // 3200000
    int nblk = (n + 255) / 256;  // <= 512

    k_init<<<(n + 255) / 256, 256>>>(n);
    k_gemm<<<(n + BM - 1) / BM, 256>>>(feat, W, al_w, al_b, ar_w, ar_b, n);
    k_edge1<<<(e / 4 + 255) / 256, 256>>>(row, e);
    k_scan1<<<nblk, 256>>>(n);
    k_scan2<<<1, 512>>>(nblk);
    k_scan3<<<nblk, 256>>>(n);
    k_edge2<<<(e + 255) / 256, 256>>>(row, col, e);
    k_spmm<<<(n * 32 + 255) / 256, 256>>>(bias, out, n);
}

// round 4
// speedup vs baseline: 1.5827x; 1.5827x over previous
#include <cuda_runtime.h>
#include <math_constants.h>
#include <cstdint>

#define DIN  256
#define DOUT 128
#define NMAX 100000
#define EMAX 3200000
#define ALPHA 0.2f

// ---- scratch (static device globals; no allocation) ----
__device__ float  g_seq[(size_t)NMAX * DOUT];  // seq_fts = feat @ W
__device__ float  g_f1[NMAX];
__device__ float  g_f2[NMAX];
__device__ int    g_cnt[NMAX];                 // per-row edge count
__device__ int    g_off[NMAX];                 // exclusive prefix (row start)
__device__ int    g_cur[NMAX];                 // scatter cursor; ends as row end
__device__ int    g_bsum[512];                 // scan block partials
__device__ float2 g_epair[EMAX];               // CSR: (col bits, e=exp(logit))

__device__ __forceinline__ uint32_t f2tf32(float f) {
    uint32_t r;
    asm("cvt.rna.tf32.f32 %0, %1;" : "=r"(r) : "f"(f));
    return r;
}

// ---------------------------------------------------------------------------
// 0) init: cnt = 0, f1/f2 = biases (GEMM epilogue atomically accumulates)
__global__ void k_init(const float* __restrict__ al_b,
                       const float* __restrict__ ar_b, int n) {
    int i = blockIdx.x * blockDim.x + threadIdx.x;
    if (i < n) { g_cnt[i] = 0; g_f1[i] = al_b[0]; g_f2[i] = ar_b[0]; }
}

// ---------------------------------------------------------------------------
// 1) tf32 tensor-core GEMM: g_seq[n,128] = feat[n,256] @ W[256,128]
//    + fused f1/f2 epilogue.
// CTA tile 128x128, BK=32, 8 warps (4 m x 2 n), warp tile 32x64,
// mma.m16n8k8.tf32, smem stride 136 floats (bank = 8k+idx: conflict-free frags)
#define SSTR 136
__global__ __launch_bounds__(256) void k_gemm(const float* __restrict__ A,
                                              const float* __restrict__ W,
                                              const float* __restrict__ al_w,
                                              const float* __restrict__ ar_w,
                                              int n) {
    __shared__ float As[32][SSTR];   // [k][m]
    __shared__ float Bs[32][SSTR];   // [k][n]

    int tid  = threadIdx.x;
    int wid  = tid >> 5;
    int lane = tid & 31;
    int warp_m = wid & 3;            // 0..3 -> 32 rows each
    int warp_n = wid >> 2;           // 0..1 -> 64 cols each
    int group  = lane >> 2;          // 0..7
    int tig    = lane & 3;           // 0..3
    int rowBase = blockIdx.x * 128;

    float acc[2][8][4];
    #pragma unroll
    for (int mt = 0; mt < 2; mt++)
        #pragma unroll
        for (int nt = 0; nt < 8; nt++)
            #pragma unroll
            for (int q = 0; q < 4; q++) acc[mt][nt][q] = 0.0f;

    int arow = tid >> 1;             // 0..127
    int aqb  = (tid & 1) * 4;        // quad base 0 or 4

    for (int k0 = 0; k0 < DIN; k0 += 32) {
        // stage A tile (transposed into [k][m])
        #pragma unroll
        for (int i = 0; i < 4; i++) {
            int q  = aqb + i;                       // 0..7 (float4 index in 32-float row)
            int gr = rowBase + arow;
            float4 v = make_float4(0.f, 0.f, 0.f, 0.f);
            if (gr < n) v = *(const float4*)(A + (size_t)gr * DIN + k0 + q * 4);
            As[q * 4 + 0][arow] = v.x;
            As[q * 4 + 1][arow] = v.y;
            As[q * 4 + 2][arow] = v.z;
            As[q * 4 + 3][arow] = v.w;
        }
        // stage B tile ([k][n], direct)
        #pragma unroll
        for (int i = 0; i < 4; i++) {
            int idx = tid + 256 * i;                // 0..1023
            int kk  = idx >> 5;
            int nq  = idx & 31;
            *(float4*)&Bs[kk][nq * 4] = *(const float4*)(W + (size_t)(k0 + kk) * DOUT + nq * 4);
        }
        __syncthreads();

        #pragma unroll
        for (int ks = 0; ks < 4; ks++) {
            int kb = ks * 8;
            uint32_t af[2][4];
            #pragma unroll
            for (int mt = 0; mt < 2; mt++) {
                int m = warp_m * 32 + mt * 16 + group;
                af[mt][0] = f2tf32(As[kb + tig][m]);
                af[mt][1] = f2tf32(As[kb + tig][m + 8]);
                af[mt][2] = f2tf32(As[kb + tig + 4][m]);
                af[mt][3] = f2tf32(As[kb + tig + 4][m + 8]);
            }
            uint32_t bf[8][2];
            #pragma unroll
            for (int nt = 0; nt < 8; nt++) {
                int nn = warp_n * 64 + nt * 8 + group;
                bf[nt][0] = f2tf32(Bs[kb + tig][nn]);
                bf[nt][1] = f2tf32(Bs[kb + tig + 4][nn]);
            }
            #pragma unroll
            for (int mt = 0; mt < 2; mt++)
                #pragma unroll
                for (int nt = 0; nt < 8; nt++) {
                    asm volatile(
                        "mma.sync.aligned.m16n8k8.row.col.f32.tf32.tf32.f32 "
                        "{%0,%1,%2,%3}, {%4,%5,%6,%7}, {%8,%9}, {%0,%1,%2,%3};"
                        : "+f"(acc[mt][nt][0]), "+f"(acc[mt][nt][1]),
                          "+f"(acc[mt][nt][2]), "+f"(acc[mt][nt][3])
                        : "r"(af[mt][0]), "r"(af[mt][1]), "r"(af[mt][2]), "r"(af[mt][3]),
                          "r"(bf[nt][0]), "r"(bf[nt][1]));
                }
        }
        __syncthreads();
    }

    // ---- store seq_fts (float2 per mma tile row-half) ----
    #pragma unroll
    for (int mt = 0; mt < 2; mt++) {
        int r0 = rowBase + warp_m * 32 + mt * 16 + group;
        #pragma unroll
        for (int nt = 0; nt < 8; nt++) {
            int cc = warp_n * 64 + nt * 8 + tig * 2;
            if (r0 < n)
                *(float2*)(g_seq + (size_t)r0 * DOUT + cc) = make_float2(acc[mt][nt][0], acc[mt][nt][1]);
            if (r0 + 8 < n)
                *(float2*)(g_seq + (size_t)(r0 + 8) * DOUT + cc) = make_float2(acc[mt][nt][2], acc[mt][nt][3]);
        }
    }

    // ---- fused f1/f2: partial dot over this warp's 64 cols, 4-lane reduce,
    //      atomicAdd into bias-initialized g_f1/g_f2 (2 warps per row) ----
    float awv[16], rwv[16];
    #pragma unroll
    for (int nt = 0; nt < 8; nt++) {
        int cc = warp_n * 64 + nt * 8 + tig * 2;
        float2 a2 = *(const float2*)(al_w + cc);
        float2 r2 = *(const float2*)(ar_w + cc);
        awv[nt * 2] = a2.x; awv[nt * 2 + 1] = a2.y;
        rwv[nt * 2] = r2.x; rwv[nt * 2 + 1] = r2.y;
    }
    #pragma unroll
    for (int mt = 0; mt < 2; mt++) {
        #pragma unroll
        for (int half = 0; half < 2; half++) {
            int gr = rowBase + warp_m * 32 + mt * 16 + group + half * 8;
            float s1 = 0.f, s2 = 0.f;
            #pragma unroll
            for (int nt = 0; nt < 8; nt++) {
                float v0 = acc[mt][nt][half * 2];
                float v1 = acc[mt][nt][half * 2 + 1];
                s1 += v0 * awv[nt * 2] + v1 * awv[nt * 2 + 1];
                s2 += v0 * rwv[nt * 2] + v1 * rwv[nt * 2 + 1];
            }
            s1 += __shfl_xor_sync(0xFFFFFFFFu, s1, 1);
            s1 += __shfl_xor_sync(0xFFFFFFFFu, s1, 2);
            s2 += __shfl_xor_sync(0xFFFFFFFFu, s2, 1);
            s2 += __shfl_xor_sync(0xFFFFFFFFu, s2, 2);
            if (tig == 0 && gr < n) {
                atomicAdd(&g_f1[gr], s1);
                atomicAdd(&g_f2[gr], s2);
            }
        }
    }
}

// ---------------------------------------------------------------------------
// 2) edge pass 1: per-row edge count (vectorized x4)
__global__ void k_edge1(const int* __restrict__ row, int e) {
    int i = (blockIdx.x * blockDim.x + threadIdx.x) * 4;
    if (i + 4 <= e) {
        int4 r4 = *(const int4*)(row + i);
        atomicAdd(&g_cnt[r4.x], 1);
        atomicAdd(&g_cnt[r4.y], 1);
        atomicAdd(&g_cnt[r4.z], 1);
        atomicAdd(&g_cnt[r4.w], 1);
    } else {
        for (int k = i; k < e; k++) atomicAdd(&g_cnt[row[k]], 1);
    }
}

// ---------------------------------------------------------------------------
// 3) 3-kernel exclusive scan over g_cnt -> g_off (+ g_cur copy)
__global__ void k_scan1(int n) {
    __shared__ int sh[256];
    int t = threadIdx.x;
    int i = blockIdx.x * 256 + t;
    int v = (i < n) ? g_cnt[i] : 0;
    sh[t] = v;
    __syncthreads();
    #pragma unroll
    for (int o = 1; o < 256; o <<= 1) {
        int x = (t >= o) ? sh[t - o] : 0;
        __syncthreads();
        sh[t] += x;
        __syncthreads();
    }
    if (i < n) g_off[i] = sh[t] - v;
    if (t == 255) g_bsum[blockIdx.x] = sh[255];
}

__global__ void k_scan2(int nblk) {
    __shared__ int sh[512];
    int t = threadIdx.x;
    int v = (t < nblk) ? g_bsum[t] : 0;
    sh[t] = v;
    __syncthreads();
    #pragma unroll
    for (int o = 1; o < 512; o <<= 1) {
        int x = (t >= o) ? sh[t - o] : 0;
        __syncthreads();
        sh[t] += x;
        __syncthreads();
    }
    if (t < nblk) g_bsum[t] = sh[t] - v;
}

__global__ void k_scan3(int n) {
    int i = blockIdx.x * blockDim.x + threadIdx.x;
    if (i >= n) return;
    int o = g_off[i] + g_bsum[i >> 8];
    g_off[i] = o;
    g_cur[i] = o;
}

// ---------------------------------------------------------------------------
// 4) edge pass 2: e = exp(leaky_relu(f1[r]+f2[c])); scatter (c,e).
//    (per-row sum s is folded into the SpMM — one atomic per edge here)
__global__ void k_edge2(const int* __restrict__ row, const int* __restrict__ col, int e) {
    int i = blockIdx.x * blockDim.x + threadIdx.x;
    if (i >= e) return;
    int r = row[i], c = col[i];
    float x = g_f1[r] + g_f2[c];
    float l = x > 0.0f ? x : ALPHA * x;
    float ev = __expf(l);
    int pos = atomicAdd(&g_cur[r], 1);
    g_epair[pos] = make_float2(__int_as_float(c), ev);
}

// ---------------------------------------------------------------------------
// 5) CSR SpMM: one warp per node; s summed inline (p.y is lane-uniform)
__global__ __launch_bounds__(256) void k_spmm(const float* __restrict__ bias,
                                              float* __restrict__ out, int n) {
    int gw   = (blockIdx.x * blockDim.x + threadIdx.x) >> 5;
    int lane = threadIdx.x & 31;
    if (gw >= n) return;
    int j0  = g_off[gw];
    int end = g_cur[gw];
    int j   = j0;

    float4 acc = make_float4(0.f, 0.f, 0.f, 0.f);
    float ssum = 0.0f;

    for (; j + 4 <= end; j += 4) {
        float2 p0 = g_epair[j],     p1 = g_epair[j + 1];
        float2 p2 = g_epair[j + 2], p3 = g_epair[j + 3];
        float4 v0 = ((const float4*)(g_seq + (size_t)__float_as_int(p0.x) * DOUT))[lane];
        float4 v1 = ((const float4*)(g_seq + (size_t)__float_as_int(p1.x) * DOUT))[lane];
        float4 v2 = ((const float4*)(g_seq + (size_t)__float_as_int(p2.x) * DOUT))[lane];
        float4 v3 = ((const float4*)(g_seq + (size_t)__float_as_int(p3.x) * DOUT))[lane];
        ssum += p0.y + p1.y + p2.y + p3.y;
        acc.x += p0.y * v0.x + p1.y * v1.x + p2.y * v2.x + p3.y * v3.x;
        acc.y += p0.y * v0.y + p1.y * v1.y + p2.y * v2.y + p3.y * v3.y;
        acc.z += p0.y * v0.z + p1.y * v1.z + p2.y * v2.z + p3.y * v3.z;
        acc.w += p0.y * v0.w + p1.y * v1.w + p2.y * v2.w + p3.y * v3.w;
    }
    for (; j < end; j++) {
        float2 p = g_epair[j];
        float4 v = ((const float4*)(g_seq + (size_t)__float_as_int(p.x) * DOUT))[lane];
        ssum += p.y;
        acc.x += p.y * v.x; acc.y += p.y * v.y;
        acc.z += p.y * v.z; acc.w += p.y * v.w;
    }

    float inv = (end > j0) ? 1.0f / ssum : 0.0f;
    float4 b = ((const float4*)bias)[lane];
    acc.x = acc.x * inv + b.x;
    acc.y = acc.y * inv + b.y;
    acc.z = acc.z * inv + b.z;
    acc.w = acc.w * inv + b.w;
    ((float4*)(out + (size_t)gw * DOUT))[lane] = acc;
}

// ---------------------------------------------------------------------------
extern "C" void kernel_launch(void* const* d_in, const int* in_sizes, int n_in,
                              void* d_out, int out_size) {
    const float* feat = (const float*)d_in[0];
    const int*   row  = (const int*)  d_in[1];
    const int*   col  = (const int*)  d_in[2];
    const float* W    = (const float*)d_in[3];
    const float* al_w = (const float*)d_in[4];
    const float* al_b = (const float*)d_in[5];
    const float* ar_w = (const float*)d_in[6];
    const float* ar_b = (const float*)d_in[7];
    const float* bias = (const float*)d_in[8];
    float* out = (float*)d_out;

    int n = in_sizes[0] / DIN;   // 100000
    int e = in_sizes[1];         // 3200000
    int nblk = (n + 255) / 256;  // <= 512

    k_init<<<(n + 255) / 256, 256>>>(al_b, ar_b, n);
    k_gemm<<<(n + 127) / 128, 256>>>(feat, W, al_w, ar_w, n);
    k_edge1<<<(e / 4 + 255) / 256, 256>>>(row, e);
    k_scan1<<<nblk, 256>>>(n);
    k_scan2<<<1, 512>>>(nblk);
    k_scan3<<<nblk, 256>>>(n);
    k_edge2<<<(e + 255) / 256, 256>>>(row, col, e);
    k_spmm<<<(n * 32 + 255) / 256, 256>>>(bias, out, n);
}

// round 6
// speedup vs baseline: 1.6085x; 1.0163x over previous
#include <cuda_runtime.h>
#include <math_constants.h>
#include <cstdint>

#define DIN  256
#define DOUT 128
#define NMAX 100000
#define EMAX 3200000
#define ALPHA 0.2f

// ---- scratch (static device globals; no allocation) ----
__device__ float  g_seq[(size_t)NMAX * DOUT];  // seq_fts = feat @ W
__device__ float  g_f1[NMAX];
__device__ float  g_f2[NMAX];
__device__ int    g_cnt[NMAX];                 // per-row edge count
__device__ int    g_off[NMAX];                 // exclusive prefix (row start)
__device__ int    g_cur[NMAX];                 // scatter cursor; ends as row end
__device__ int    g_bsum[512];                 // scan block partials
__device__ int    g_ecol[EMAX];                // CSR: col index per edge

__device__ __forceinline__ uint32_t f2tf32(float f) {
    uint32_t r;
    asm("cvt.rna.tf32.f32 %0, %1;" : "=r"(r) : "f"(f));
    return r;
}

// ---------------------------------------------------------------------------
// 0) init: cnt = 0
__global__ void k_init(int n) {
    int i = blockIdx.x * blockDim.x + threadIdx.x;
    if (i < n) g_cnt[i] = 0;
}

// ---------------------------------------------------------------------------
// 1) tf32 tensor-core GEMM: g_seq[n,128] = feat[n,256] @ W[256,128]
//    + fused f1/f2 epilogue (smem cross-warp reduce, no atomics).
#define SSTR 136
__global__ __launch_bounds__(256) void k_gemm(const float* __restrict__ A,
                                              const float* __restrict__ W,
                                              const float* __restrict__ al_w,
                                              const float* __restrict__ al_b,
                                              const float* __restrict__ ar_w,
                                              const float* __restrict__ ar_b,
                                              int n) {
    __shared__ float As[32][SSTR];   // [k][m]
    __shared__ float Bs[32][SSTR];   // [k][n]

    int tid  = threadIdx.x;
    int wid  = tid >> 5;
    int lane = tid & 31;
    int warp_m = wid & 3;            // 0..3 -> 32 rows each
    int warp_n = wid >> 2;           // 0..1 -> 64 cols each
    int group  = lane >> 2;          // 0..7
    int tig    = lane & 3;           // 0..3
    int rowBase = blockIdx.x * 128;

    float acc[2][8][4];
    #pragma unroll
    for (int mt = 0; mt < 2; mt++)
        #pragma unroll
        for (int nt = 0; nt < 8; nt++)
            #pragma unroll
            for (int q = 0; q < 4; q++) acc[mt][nt][q] = 0.0f;

    int arow = tid >> 1;             // 0..127
    int aqb  = (tid & 1) * 4;        // quad base 0 or 4

    for (int k0 = 0; k0 < DIN; k0 += 32) {
        #pragma unroll
        for (int i = 0; i < 4; i++) {
            int q  = aqb + i;
            int gr = rowBase + arow;
            float4 v = make_float4(0.f, 0.f, 0.f, 0.f);
            if (gr < n) v = *(const float4*)(A + (size_t)gr * DIN + k0 + q * 4);
            As[q * 4 + 0][arow] = v.x;
            As[q * 4 + 1][arow] = v.y;
            As[q * 4 + 2][arow] = v.z;
            As[q * 4 + 3][arow] = v.w;
        }
        #pragma unroll
        for (int i = 0; i < 4; i++) {
            int idx = tid + 256 * i;
            int kk  = idx >> 5;
            int nq  = idx & 31;
            *(float4*)&Bs[kk][nq * 4] = *(const float4*)(W + (size_t)(k0 + kk) * DOUT + nq * 4);
        }
        __syncthreads();

        #pragma unroll
        for (int ks = 0; ks < 4; ks++) {
            int kb = ks * 8;
            uint32_t af[2][4];
            #pragma unroll
            for (int mt = 0; mt < 2; mt++) {
                int m = warp_m * 32 + mt * 16 + group;
                af[mt][0] = f2tf32(As[kb + tig][m]);
                af[mt][1] = f2tf32(As[kb + tig][m + 8]);
                af[mt][2] = f2tf32(As[kb + tig + 4][m]);
                af[mt][3] = f2tf32(As[kb + tig + 4][m + 8]);
            }
            uint32_t bf[8][2];
            #pragma unroll
            for (int nt = 0; nt < 8; nt++) {
                int nn = warp_n * 64 + nt * 8 + group;
                bf[nt][0] = f2tf32(Bs[kb + tig][nn]);
                bf[nt][1] = f2tf32(Bs[kb + tig + 4][nn]);
            }
            #pragma unroll
            for (int mt = 0; mt < 2; mt++)
                #pragma unroll
                for (int nt = 0; nt < 8; nt++) {
                    asm volatile(
                        "mma.sync.aligned.m16n8k8.row.col.f32.tf32.tf32.f32 "
                        "{%0,%1,%2,%3}, {%4,%5,%6,%7}, {%8,%9}, {%0,%1,%2,%3};"
                        : "+f"(acc[mt][nt][0]), "+f"(acc[mt][nt][1]),
                          "+f"(acc[mt][nt][2]), "+f"(acc[mt][nt][3])
                        : "r"(af[mt][0]), "r"(af[mt][1]), "r"(af[mt][2]), "r"(af[mt][3]),
                          "r"(bf[nt][0]), "r"(bf[nt][1]));
                }
        }
        __syncthreads();
    }

    // ---- store seq_fts ----
    #pragma unroll
    for (int mt = 0; mt < 2; mt++) {
        int r0 = rowBase + warp_m * 32 + mt * 16 + group;
        #pragma unroll
        for (int nt = 0; nt < 8; nt++) {
            int cc = warp_n * 64 + nt * 8 + tig * 2;
            if (r0 < n)
                *(float2*)(g_seq + (size_t)r0 * DOUT + cc) = make_float2(acc[mt][nt][0], acc[mt][nt][1]);
            if (r0 + 8 < n)
                *(float2*)(g_seq + (size_t)(r0 + 8) * DOUT + cc) = make_float2(acc[mt][nt][2], acc[mt][nt][3]);
        }
    }

    // ---- fused f1/f2: per-warp partial (64 cols), 4-lane shfl reduce,
    //      cross-warp (warp_n 0 vs 1) combine through smem, single store ----
    float awv[16], rwv[16];
    #pragma unroll
    for (int nt = 0; nt < 8; nt++) {
        int cc = warp_n * 64 + nt * 8 + tig * 2;
        float2 a2 = *(const float2*)(al_w + cc);
        float2 r2 = *(const float2*)(ar_w + cc);
        awv[nt * 2] = a2.x; awv[nt * 2 + 1] = a2.y;
        rwv[nt * 2] = r2.x; rwv[nt * 2 + 1] = r2.y;
    }

    float* smf = &As[0][0];          // repurpose: smf[0..127]=f1, smf[128..255]=f2
    float p1[2][2], p2[2][2];
    #pragma unroll
    for (int mt = 0; mt < 2; mt++) {
        #pragma unroll
        for (int half = 0; half < 2; half++) {
            float s1 = 0.f, s2 = 0.f;
            #pragma unroll
            for (int nt = 0; nt < 8; nt++) {
                float v0 = acc[mt][nt][half * 2];
                float v1 = acc[mt][nt][half * 2 + 1];
                s1 += v0 * awv[nt * 2] + v1 * awv[nt * 2 + 1];
                s2 += v0 * rwv[nt * 2] + v1 * rwv[nt * 2 + 1];
            }
            s1 += __shfl_xor_sync(0xFFFFFFFFu, s1, 1);
            s1 += __shfl_xor_sync(0xFFFFFFFFu, s1, 2);
            s2 += __shfl_xor_sync(0xFFFFFFFFu, s2, 1);
            s2 += __shfl_xor_sync(0xFFFFFFFFu, s2, 2);
            p1[mt][half] = s1; p2[mt][half] = s2;
        }
    }
    __syncthreads();                 // As reads done; safe to repurpose
    if (warp_n == 0 && tig == 0) {
        #pragma unroll
        for (int mt = 0; mt < 2; mt++)
            #pragma unroll
            for (int half = 0; half < 2; half++) {
                int lr = warp_m * 32 + mt * 16 + group + half * 8;
                smf[lr]       = p1[mt][half];
                smf[128 + lr] = p2[mt][half];
            }
    }
    __syncthreads();
    if (warp_n == 1 && tig == 0) {
        float ab = al_b[0], rb = ar_b[0];
        #pragma unroll
        for (int mt = 0; mt < 2; mt++)
            #pragma unroll
            for (int half = 0; half < 2; half++) {
                int lr = warp_m * 32 + mt * 16 + group + half * 8;
                int gr = rowBase + lr;
                if (gr < n) {
                    g_f1[gr] = smf[lr]       + p1[mt][half] + ab;
                    g_f2[gr] = smf[128 + lr] + p2[mt][half] + rb;
                }
            }
    }
}

// ---------------------------------------------------------------------------
// 2) edge pass 1: per-row edge count (vectorized x4)
__global__ void k_edge1(const int* __restrict__ row, int e) {
    int i = (blockIdx.x * blockDim.x + threadIdx.x) * 4;
    if (i + 4 <= e) {
        int4 r4 = *(const int4*)(row + i);
        atomicAdd(&g_cnt[r4.x], 1);
        atomicAdd(&g_cnt[r4.y], 1);
        atomicAdd(&g_cnt[r4.z], 1);
        atomicAdd(&g_cnt[r4.w], 1);
    } else {
        for (int k = i; k < e; k++) atomicAdd(&g_cnt[row[k]], 1);
    }
}

// ---------------------------------------------------------------------------
// 3) 3-kernel exclusive scan over g_cnt -> g_off (+ g_cur copy)
__global__ void k_scan1(int n) {
    __shared__ int sh[256];
    int t = threadIdx.x;
    int i = blockIdx.x * 256 + t;
    int v = (i < n) ? g_cnt[i] : 0;
    sh[t] = v;
    __syncthreads();
    #pragma unroll
    for (int o = 1; o < 256; o <<= 1) {
        int x = (t >= o) ? sh[t - o] : 0;
        __syncthreads();
        sh[t] += x;
        __syncthreads();
    }
    if (i < n) g_off[i] = sh[t] - v;
    if (t == 255) g_bsum[blockIdx.x] = sh[255];
}

__global__ void k_scan2(int nblk) {
    __shared__ int sh[512];
    int t = threadIdx.x;
    int v = (t < nblk) ? g_bsum[t] : 0;
    sh[t] = v;
    __syncthreads();
    #pragma unroll
    for (int o = 1; o < 512; o <<= 1) {
        int x = (t >= o) ? sh[t - o] : 0;
        __syncthreads();
        sh[t] += x;
        __syncthreads();
    }
    if (t < nblk) g_bsum[t] = sh[t] - v;
}

__global__ void k_scan3(int n) {
    int i = blockIdx.x * blockDim.x + threadIdx.x;
    if (i >= n) return;
    int o = g_off[i] + g_bsum[i >> 8];
    g_off[i] = o;
    g_cur[i] = o;
}

// ---------------------------------------------------------------------------
// 4) edge pass 2: pure CSR permutation — scatter col only (x4 vectorized)
__global__ void k_edge2(const int* __restrict__ row, const int* __restrict__ col, int e) {
    int i = (blockIdx.x * blockDim.x + threadIdx.x) * 4;
    if (i + 4 <= e) {
        int4 r4 = *(const int4*)(row + i);
        int4 c4 = *(const int4*)(col + i);
        int p0 = atomicAdd(&g_cur[r4.x], 1);
        int p1 = atomicAdd(&g_cur[r4.y], 1);
        int p2 = atomicAdd(&g_cur[r4.z], 1);
        int p3 = atomicAdd(&g_cur[r4.w], 1);
        g_ecol[p0] = c4.x; g_ecol[p1] = c4.y;
        g_ecol[p2] = c4.z; g_ecol[p3] = c4.w;
    } else {
        for (int k = i; k < e; k++) {
            int p = atomicAdd(&g_cur[row[k]], 1);
            g_ecol[p] = col[k];
        }
    }
}

// ---------------------------------------------------------------------------
// 5) CSR SpMM + fused softmax: one warp per node.
//    e_j = exp(leaky(f1[node] + f2[col_j])); out = (Σ e_j seq[col_j])/Σe + bias
//    NOTE: row start j0 is only 4B-aligned -> peel to 16B before int4 loads.
__global__ __launch_bounds__(256) void k_spmm(const float* __restrict__ bias,
                                              float* __restrict__ out, int n) {
    int gw   = (blockIdx.x * blockDim.x + threadIdx.x) >> 5;
    int lane = threadIdx.x & 31;
    if (gw >= n) return;
    int j0  = g_off[gw];
    int end = g_cur[gw];
    int j   = j0;

    float f1v = g_f1[gw];            // warp-uniform
    float4 acc = make_float4(0.f, 0.f, 0.f, 0.f);
    float ssum = 0.0f;

    // scalar peel to 16B alignment
    while (j < end && (j & 3)) {
        int c = g_ecol[j];
        float x = f1v + g_f2[c];
        float ev = __expf(x > 0.f ? x : ALPHA * x);
        float4 v = ((const float4*)(g_seq + (size_t)c * DOUT))[lane];
        ssum += ev;
        acc.x += ev * v.x; acc.y += ev * v.y;
        acc.z += ev * v.z; acc.w += ev * v.w;
        j++;
    }

    for (; j + 4 <= end; j += 4) {
        int4 c4 = *(const int4*)(g_ecol + j);            // 16B-aligned now
        float w0 = g_f2[c4.x], w1 = g_f2[c4.y];
        float w2 = g_f2[c4.z], w3 = g_f2[c4.w];
        float4 v0 = ((const float4*)(g_seq + (size_t)c4.x * DOUT))[lane];
        float4 v1 = ((const float4*)(g_seq + (size_t)c4.y * DOUT))[lane];
        float4 v2 = ((const float4*)(g_seq + (size_t)c4.z * DOUT))[lane];
        float4 v3 = ((const float4*)(g_seq + (size_t)c4.w * DOUT))[lane];
        float x0 = f1v + w0, x1 = f1v + w1, x2 = f1v + w2, x3 = f1v + w3;
        float e0 = __expf(x0 > 0.f ? x0 : ALPHA * x0);
        float e1 = __expf(x1 > 0.f ? x1 : ALPHA * x1);
        float e2 = __expf(x2 > 0.f ? x2 : ALPHA * x2);
        float e3 = __expf(x3 > 0.f ? x3 : ALPHA * x3);
        ssum += e0 + e1 + e2 + e3;
        acc.x += e0 * v0.x + e1 * v1.x + e2 * v2.x + e3 * v3.x;
        acc.y += e0 * v0.y + e1 * v1.y + e2 * v2.y + e3 * v3.y;
        acc.z += e0 * v0.z + e1 * v1.z + e2 * v2.z + e3 * v3.z;
        acc.w += e0 * v0.w + e1 * v1.w + e2 * v2.w + e3 * v3.w;
    }
    for (; j < end; j++) {
        int c = g_ecol[j];
        float x = f1v + g_f2[c];
        float ev = __expf(x > 0.f ? x : ALPHA * x);
        float4 v = ((const float4*)(g_seq + (size_t)c * DOUT))[lane];
        ssum += ev;
        acc.x += ev * v.x; acc.y += ev * v.y;
        acc.z += ev * v.z; acc.w += ev * v.w;
    }

    float inv = (end > j0) ? 1.0f / ssum : 0.0f;
    float4 b = ((const float4*)bias)[lane];
    acc.x = acc.x * inv + b.x;
    acc.y = acc.y * inv + b.y;
    acc.z = acc.z * inv + b.z;
    acc.w = acc.w * inv + b.w;
    ((float4*)(out + (size_t)gw * DOUT))[lane] = acc;
}

// ---------------------------------------------------------------------------
extern "C" void kernel_launch(void* const* d_in, const int* in_sizes, int n_in,
                              void* d_out, int out_size) {
    const float* feat = (const float*)d_in[0];
    const int*   row  = (const int*)  d_in[1];
    const int*   col  = (const int*)  d_in[2];
    const float* W    = (const float*)d_in[3];
    const float* al_w = (const float*)d_in[4];
    const float* al_b = (const float*)d_in[5];
    const float* ar_w = (const float*)d_in[6];
    const float* ar_b = (const float*)d_in[7];
    const float* bias = (const float*)d_in[8];
    float* out = (float*)d_out;

    int n = in_sizes[0] / DIN;   // 100000
    int e = in_sizes[1];         // 3200000
    int nblk = (n + 255) / 256;  // <= 512

    k_init<<<(n + 255) / 256, 256>>>(n);
    k_edge1<<<(e / 4 + 255) / 256, 256>>>(row, e);
    k_gemm<<<(n + 127) / 128, 256>>>(feat, W, al_w, al_b, ar_w, ar_b, n);
    k_scan1<<<nblk, 256>>>(n);
    k_scan2<<<1, 512>>>(nblk);
    k_scan3<<<nblk, 256>>>(n);
    k_edge2<<<(e / 4 + 255) / 256, 256>>>(row, col, e);
    k_spmm<<<(n * 32 + 255) / 256, 256>>>(bias, out, n);
}

// round 7
// speedup vs baseline: 1.6321x; 1.0147x over previous
#include <cuda_runtime.h>
#include <cuda_fp16.h>
#include <math_constants.h>
#include <cstdint>

#define DIN  256
#define DOUT 128
#define NMAX 100000
#define EMAX 3200000
#define ALPHA 0.2f

// ---- scratch (static device globals; no allocation) ----
__device__ __half  g_seqh[(size_t)NMAX * DOUT]; // seq_fts = feat @ W (fp16 storage)
__device__ float   g_f1[NMAX];
__device__ float   g_f2[NMAX];
__device__ int     g_cnt[NMAX];                 // per-row edge count
__device__ int     g_off[NMAX];                 // exclusive prefix (row start)
__device__ int     g_cur[NMAX];                 // scatter cursor; ends as row end
__device__ int     g_bsum[512];                 // scan block partials
__device__ int     g_ecol[EMAX];                // CSR: col index per edge

__device__ __forceinline__ uint32_t f2tf32(float f) {
    uint32_t r;
    asm("cvt.rna.tf32.f32 %0, %1;" : "=r"(r) : "f"(f));
    return r;
}

// lane reads 4 halves (8B) of a 128-col fp16 row, returns as float4
__device__ __forceinline__ float4 ldrow_h(const __half* base, int lane) {
    uint2 u = ((const uint2*)base)[lane];
    __half2 h0 = *reinterpret_cast<__half2*>(&u.x);
    __half2 h1 = *reinterpret_cast<__half2*>(&u.y);
    float2 a = __half22float2(h0);
    float2 b = __half22float2(h1);
    return make_float4(a.x, a.y, b.x, b.y);
}

// ---------------------------------------------------------------------------
// 0) init: cnt = 0
__global__ void k_init(int n) {
    int i = blockIdx.x * blockDim.x + threadIdx.x;
    if (i < n) g_cnt[i] = 0;
}

// ---------------------------------------------------------------------------
// 1) tf32 tensor-core GEMM: g_seqh[n,128] = fp16(feat[n,256] @ W[256,128])
//    + fused f1/f2 epilogue (from fp32 accumulators, smem cross-warp reduce).
#define SSTR 136
__global__ __launch_bounds__(256) void k_gemm(const float* __restrict__ A,
                                              const float* __restrict__ W,
                                              const float* __restrict__ al_w,
                                              const float* __restrict__ al_b,
                                              const float* __restrict__ ar_w,
                                              const float* __restrict__ ar_b,
                                              int n) {
    __shared__ float As[32][SSTR];   // [k][m]
    __shared__ float Bs[32][SSTR];   // [k][n]

    int tid  = threadIdx.x;
    int wid  = tid >> 5;
    int lane = tid & 31;
    int warp_m = wid & 3;            // 0..3 -> 32 rows each
    int warp_n = wid >> 2;           // 0..1 -> 64 cols each
    int group  = lane >> 2;          // 0..7
    int tig    = lane & 3;           // 0..3
    int rowBase = blockIdx.x * 128;

    float acc[2][8][4];
    #pragma unroll
    for (int mt = 0; mt < 2; mt++)
        #pragma unroll
        for (int nt = 0; nt < 8; nt++)
            #pragma unroll
            for (int q = 0; q < 4; q++) acc[mt][nt][q] = 0.0f;

    int arow = tid >> 1;             // 0..127
    int aqb  = (tid & 1) * 4;        // quad base 0 or 4

    for (int k0 = 0; k0 < DIN; k0 += 32) {
        #pragma unroll
        for (int i = 0; i < 4; i++) {
            int q  = aqb + i;
            int gr = rowBase + arow;
            float4 v = make_float4(0.f, 0.f, 0.f, 0.f);
            if (gr < n) v = *(const float4*)(A + (size_t)gr * DIN + k0 + q * 4);
            As[q * 4 + 0][arow] = v.x;
            As[q * 4 + 1][arow] = v.y;
            As[q * 4 + 2][arow] = v.z;
            As[q * 4 + 3][arow] = v.w;
        }
        #pragma unroll
        for (int i = 0; i < 4; i++) {
            int idx = tid + 256 * i;
            int kk  = idx >> 5;
            int nq  = idx & 31;
            *(float4*)&Bs[kk][nq * 4] = *(const float4*)(W + (size_t)(k0 + kk) * DOUT + nq * 4);
        }
        __syncthreads();

        #pragma unroll
        for (int ks = 0; ks < 4; ks++) {
            int kb = ks * 8;
            uint32_t af[2][4];
            #pragma unroll
            for (int mt = 0; mt < 2; mt++) {
                int m = warp_m * 32 + mt * 16 + group;
                af[mt][0] = f2tf32(As[kb + tig][m]);
                af[mt][1] = f2tf32(As[kb + tig][m + 8]);
                af[mt][2] = f2tf32(As[kb + tig + 4][m]);
                af[mt][3] = f2tf32(As[kb + tig + 4][m + 8]);
            }
            uint32_t bf[8][2];
            #pragma unroll
            for (int nt = 0; nt < 8; nt++) {
                int nn = warp_n * 64 + nt * 8 + group;
                bf[nt][0] = f2tf32(Bs[kb + tig][nn]);
                bf[nt][1] = f2tf32(Bs[kb + tig + 4][nn]);
            }
            #pragma unroll
            for (int mt = 0; mt < 2; mt++)
                #pragma unroll
                for (int nt = 0; nt < 8; nt++) {
                    asm volatile(
                        "mma.sync.aligned.m16n8k8.row.col.f32.tf32.tf32.f32 "
                        "{%0,%1,%2,%3}, {%4,%5,%6,%7}, {%8,%9}, {%0,%1,%2,%3};"
                        : "+f"(acc[mt][nt][0]), "+f"(acc[mt][nt][1]),
                          "+f"(acc[mt][nt][2]), "+f"(acc[mt][nt][3])
                        : "r"(af[mt][0]), "r"(af[mt][1]), "r"(af[mt][2]), "r"(af[mt][3]),
                          "r"(bf[nt][0]), "r"(bf[nt][1]));
                }
        }
        __syncthreads();
    }

    // ---- store seq_fts as fp16 (half2 per mma fragment pair) ----
    #pragma unroll
    for (int mt = 0; mt < 2; mt++) {
        int r0 = rowBase + warp_m * 32 + mt * 16 + group;
        #pragma unroll
        for (int nt = 0; nt < 8; nt++) {
            int cc = warp_n * 64 + nt * 8 + tig * 2;
            if (r0 < n)
                *(__half2*)(g_seqh + (size_t)r0 * DOUT + cc) =
                    __floats2half2_rn(acc[mt][nt][0], acc[mt][nt][1]);
            if (r0 + 8 < n)
                *(__half2*)(g_seqh + (size_t)(r0 + 8) * DOUT + cc) =
                    __floats2half2_rn(acc[mt][nt][2], acc[mt][nt][3]);
        }
    }

    // ---- fused f1/f2 (fp32 accs): per-warp partial, 4-lane shfl reduce,
    //      cross-warp combine through smem, single store ----
    float awv[16], rwv[16];
    #pragma unroll
    for (int nt = 0; nt < 8; nt++) {
        int cc = warp_n * 64 + nt * 8 + tig * 2;
        float2 a2 = *(const float2*)(al_w + cc);
        float2 r2 = *(const float2*)(ar_w + cc);
        awv[nt * 2] = a2.x; awv[nt * 2 + 1] = a2.y;
        rwv[nt * 2] = r2.x; rwv[nt * 2 + 1] = r2.y;
    }

    float* smf = &As[0][0];          // repurpose: smf[0..127]=f1, smf[128..255]=f2
    float p1[2][2], p2[2][2];
    #pragma unroll
    for (int mt = 0; mt < 2; mt++) {
        #pragma unroll
        for (int half = 0; half < 2; half++) {
            float s1 = 0.f, s2 = 0.f;
            #pragma unroll
            for (int nt = 0; nt < 8; nt++) {
                float v0 = acc[mt][nt][half * 2];
                float v1 = acc[mt][nt][half * 2 + 1];
                s1 += v0 * awv[nt * 2] + v1 * awv[nt * 2 + 1];
                s2 += v0 * rwv[nt * 2] + v1 * rwv[nt * 2 + 1];
            }
            s1 += __shfl_xor_sync(0xFFFFFFFFu, s1, 1);
            s1 += __shfl_xor_sync(0xFFFFFFFFu, s1, 2);
            s2 += __shfl_xor_sync(0xFFFFFFFFu, s2, 1);
            s2 += __shfl_xor_sync(0xFFFFFFFFu, s2, 2);
            p1[mt][half] = s1; p2[mt][half] = s2;
        }
    }
    __syncthreads();                 // As reads done; safe to repurpose
    if (warp_n == 0 && tig == 0) {
        #pragma unroll
        for (int mt = 0; mt < 2; mt++)
            #pragma unroll
            for (int half = 0; half < 2; half++) {
                int lr = warp_m * 32 + mt * 16 + group + half * 8;
                smf[lr]       = p1[mt][half];
                smf[128 + lr] = p2[mt][half];
            }
    }
    __syncthreads();
    if (warp_n == 1 && tig == 0) {
        float ab = al_b[0], rb = ar_b[0];
        #pragma unroll
        for (int mt = 0; mt < 2; mt++)
            #pragma unroll
            for (int half = 0; half < 2; half++) {
                int lr = warp_m * 32 + mt * 16 + group + half * 8;
                int gr = rowBase + lr;
                if (gr < n) {
                    g_f1[gr] = smf[lr]       + p1[mt][half] + ab;
                    g_f2[gr] = smf[128 + lr] + p2[mt][half] + rb;
                }
            }
    }
}

// ---------------------------------------------------------------------------
// 2) edge pass 1: per-row edge count (vectorized x4)
__global__ void k_edge1(const int* __restrict__ row, int e) {
    int i = (blockIdx.x * blockDim.x + threadIdx.x) * 4;
    if (i + 4 <= e) {
        int4 r4 = *(const int4*)(row + i);
        atomicAdd(&g_cnt[r4.x], 1);
        atomicAdd(&g_cnt[r4.y], 1);
        atomicAdd(&g_cnt[r4.z], 1);
        atomicAdd(&g_cnt[r4.w], 1);
    } else {
        for (int k = i; k < e; k++) atomicAdd(&g_cnt[row[k]], 1);
    }
}

// ---------------------------------------------------------------------------
// 3) 3-kernel exclusive scan over g_cnt -> g_off (+ g_cur copy)
__global__ void k_scan1(int n) {
    __shared__ int sh[256];
    int t = threadIdx.x;
    int i = blockIdx.x * 256 + t;
    int v = (i < n) ? g_cnt[i] : 0;
    sh[t] = v;
    __syncthreads();
    #pragma unroll
    for (int o = 1; o < 256; o <<= 1) {
        int x = (t >= o) ? sh[t - o] : 0;
        __syncthreads();
        sh[t] += x;
        __syncthreads();
    }
    if (i < n) g_off[i] = sh[t] - v;
    if (t == 255) g_bsum[blockIdx.x] = sh[255];
}

__global__ void k_scan2(int nblk) {
    __shared__ int sh[512];
    int t = threadIdx.x;
    int v = (t < nblk) ? g_bsum[t] : 0;
    sh[t] = v;
    __syncthreads();
    #pragma unroll
    for (int o = 1; o < 512; o <<= 1) {
        int x = (t >= o) ? sh[t - o] : 0;
        __syncthreads();
        sh[t] += x;
        __syncthreads();
    }
    if (t < nblk) g_bsum[t] = sh[t] - v;
}

__global__ void k_scan3(int n) {
    int i = blockIdx.x * blockDim.x + threadIdx.x;
    if (i >= n) return;
    int o = g_off[i] + g_bsum[i >> 8];
    g_off[i] = o;
    g_cur[i] = o;
}

// ---------------------------------------------------------------------------
// 4) edge pass 2: pure CSR permutation — scatter col only (x4 vectorized)
__global__ void k_edge2(const int* __restrict__ row, const int* __restrict__ col, int e) {
    int i = (blockIdx.x * blockDim.x + threadIdx.x) * 4;
    if (i + 4 <= e) {
        int4 r4 = *(const int4*)(row + i);
        int4 c4 = *(const int4*)(col + i);
        int p0 = atomicAdd(&g_cur[r4.x], 1);
        int p1 = atomicAdd(&g_cur[r4.y], 1);
        int p2 = atomicAdd(&g_cur[r4.z], 1);
        int p3 = atomicAdd(&g_cur[r4.w], 1);
        g_ecol[p0] = c4.x; g_ecol[p1] = c4.y;
        g_ecol[p2] = c4.z; g_ecol[p3] = c4.w;
    } else {
        for (int k = i; k < e; k++) {
            int p = atomicAdd(&g_cur[row[k]], 1);
            g_ecol[p] = col[k];
        }
    }
}

// ---------------------------------------------------------------------------
// 5) CSR SpMM + fused softmax: one warp per node, fp16 row gather.
//    e_j = exp(leaky(f1[node] + f2[col_j])); out = (Σ e_j seq[col_j])/Σe + bias
__global__ __launch_bounds__(256) void k_spmm(const float* __restrict__ bias,
                                              float* __restrict__ out, int n) {
    int gw   = (blockIdx.x * blockDim.x + threadIdx.x) >> 5;
    int lane = threadIdx.x & 31;
    if (gw >= n) return;
    int j0  = g_off[gw];
    int end = g_cur[gw];
    int j   = j0;

    float f1v = g_f1[gw];            // warp-uniform
    float4 acc = make_float4(0.f, 0.f, 0.f, 0.f);
    float ssum = 0.0f;

    // scalar peel to 16B alignment for int4 loads of g_ecol
    while (j < end && (j & 3)) {
        int c = g_ecol[j];
        float x = f1v + g_f2[c];
        float ev = __expf(x > 0.f ? x : ALPHA * x);
        float4 v = ldrow_h(g_seqh + (size_t)c * DOUT, lane);
        ssum += ev;
        acc.x += ev * v.x; acc.y += ev * v.y;
        acc.z += ev * v.z; acc.w += ev * v.w;
        j++;
    }

    for (; j + 4 <= end; j += 4) {
        int4 c4 = *(const int4*)(g_ecol + j);
        float w0 = g_f2[c4.x], w1 = g_f2[c4.y];
        float w2 = g_f2[c4.z], w3 = g_f2[c4.w];
        float4 v0 = ldrow_h(g_seqh + (size_t)c4.x * DOUT, lane);
        float4 v1 = ldrow_h(g_seqh + (size_t)c4.y * DOUT, lane);
        float4 v2 = ldrow_h(g_seqh + (size_t)c4.z * DOUT, lane);
        float4 v3 = ldrow_h(g_seqh + (size_t)c4.w * DOUT, lane);
        float x0 = f1v + w0, x1 = f1v + w1, x2 = f1v + w2, x3 = f1v + w3;
        float e0 = __expf(x0 > 0.f ? x0 : ALPHA * x0);
        float e1 = __expf(x1 > 0.f ? x1 : ALPHA * x1);
        float e2 = __expf(x2 > 0.f ? x2 : ALPHA * x2);
        float e3 = __expf(x3 > 0.f ? x3 : ALPHA * x3);
        ssum += e0 + e1 + e2 + e3;
        acc.x += e0 * v0.x + e1 * v1.x + e2 * v2.x + e3 * v3.x;
        acc.y += e0 * v0.y + e1 * v1.y + e2 * v2.y + e3 * v3.y;
        acc.z += e0 * v0.z + e1 * v1.z + e2 * v2.z + e3 * v3.z;
        acc.w += e0 * v0.w + e1 * v1.w + e2 * v2.w + e3 * v3.w;
    }
    for (; j < end; j++) {
        int c = g_ecol[j];
        float x = f1v + g_f2[c];
        float ev = __expf(x > 0.f ? x : ALPHA * x);
        float4 v = ldrow_h(g_seqh + (size_t)c * DOUT, lane);
        ssum += ev;
        acc.x += ev * v.x; acc.y += ev * v.y;
        acc.z += ev * v.z; acc.w += ev * v.w;
    }

    float inv = (end > j0) ? 1.0f / ssum : 0.0f;
    // lane covers columns [lane*4, lane*4+4)
    float4 b = ((const float4*)bias)[lane];
    acc.x = acc.x * inv + b.x;
    acc.y = acc.y * inv + b.y;
    acc.z = acc.z * inv + b.z;
    acc.w = acc.w * inv + b.w;
    ((float4*)(out + (size_t)gw * DOUT))[lane] = acc;
}

// ---------------------------------------------------------------------------
extern "C" void kernel_launch(void* const* d_in, const int* in_sizes, int n_in,
                              void* d_out, int out_size) {
    const float* feat = (const float*)d_in[0];
    const int*   row  = (const int*)  d_in[1];
    const int*   col  = (const int*)  d_in[2];
    const float* W    = (const float*)d_in[3];
    const float* al_w = (const float*)d_in[4];
    const float* al_b = (const float*)d_in[5];
    const float* ar_w = (const float*)d_in[6];
    const float* ar_b = (const float*)d_in[7];
    const float* bias = (const float*)d_in[8];
    float* out = (float*)d_out;

    int n = in_sizes[0] / DIN;   // 100000
    int e = in_sizes[1];         // 3200000
    int nblk = (n + 255) / 256;  // <= 512

    k_init<<<(n + 255) / 256, 256>>>(n);
    k_edge1<<<(e / 4 + 255) / 256, 256>>>(row, e);
    k_gemm<<<(n + 127) / 128, 256>>>(feat, W, al_w, al_b, ar_w, ar_b, n);
    k_scan1<<<nblk, 256>>>(n);
    k_scan2<<<1, 512>>>(nblk);
    k_scan3<<<nblk, 256>>>(n);
    k_edge2<<<(e / 4 + 255) / 256, 256>>>(row, col, e);
    k_spmm<<<(n * 32 + 255) / 256, 256>>>(bias, out, n);
}